// round 14
// baseline (speedup 1.0000x reference)
#include <cuda_runtime.h>
#include <cuda_fp16.h>
#include <math.h>
#include <stdint.h>

#define B_ 256
#define S_ 120
#define T_ 24
#define D_ 216
#define H_ 1024
#define G_ 4096           // 4*H
#define KP 1280           // padded K (1024 h + 216 x + 40 zero)
#define XP 256            // padded x row width
#define BK 128
#define NCH (KP / BK)     // 10
#define A_PITCH 272                    // 256B row + 16B pad (conflict-free)
#define REGION_BYTES 17472             // 64*272 + 64B rotation
#define STAGE_BYTES (2 * REGION_BYTES) // 34944 (A region + B region)
#define NSTAGE 3
#define SMEM_DYN (NSTAGE * STAGE_BYTES)  // 104832

// ---------------- device globals (no allocations allowed) --------------------
__device__ __align__(16) __half g_Wp[G_ * KP];        // permuted fp16 weights
__device__ __align__(16) __half g_xe[S_ * B_ * XP];   // encoder x fp16
__device__ __align__(16) __half g_xd[B_ * XP];        // decoder x fp16
__device__ __align__(16) __half g_ah[2][B_ * H_];     // h fp16, ping-pong
__device__ float g_hf[B_ * H_];       // fp32 h (projection input)
__device__ float g_c[B_ * H_];        // cell state
__device__ float g_bp[G_];            // permuted combined bias
__device__ float g_proj[8][B_ * D_];  // split-K projection partials

__device__ __forceinline__ float sigf(float v) { return 1.f / (1.f + expf(-v)); }

// ---------------- PTX helpers (baseline sm_80+ only) -------------------------
__device__ __forceinline__ uint32_t smem_u32(const void* p) {
    uint32_t a;
    asm("{ .reg .u64 t; cvta.to.shared.u64 t, %1; cvt.u32.u64 %0, t; }"
        : "=r"(a) : "l"(p));
    return a;
}
#define CP_ASYNC16(dst, src) \
    asm volatile("cp.async.ca.shared.global [%0], [%1], 16;" :: "r"(dst), "l"(src))
#define CP_COMMIT() asm volatile("cp.async.commit_group;" ::: "memory")
#define CP_WAIT1()  asm volatile("cp.async.wait_group 1;" ::: "memory")
#define CP_WAIT0()  asm volatile("cp.async.wait_group 0;" ::: "memory")

#define LDSM_X4(r0, r1, r2, r3, a) \
    asm volatile("ldmatrix.sync.aligned.m8n8.x4.shared.b16 {%0,%1,%2,%3}, [%4];" \
                 : "=r"(r0), "=r"(r1), "=r"(r2), "=r"(r3) : "r"(a))

#define MMAF16(d, a, b) \
    asm volatile("mma.sync.aligned.m16n8k16.row.col.f32.f16.f16.f32 " \
                 "{%0,%1,%2,%3},{%4,%5,%6,%7},{%8,%9},{%0,%1,%2,%3};" \
                 : "+f"((d)[0]), "+f"((d)[1]), "+f"((d)[2]), "+f"((d)[3]) \
                 : "r"((a)[0]), "r"((a)[1]), "r"((a)[2]), "r"((a)[3]), \
                   "r"((b)[0]), "r"((b)[1]))

// ---------------- prep kernels ----------------------------------------------
// Permutation: permuted col p -> bn=p>>6, c=p&63, u=c>>2, q=c&3, unit j=bn*16+u,
// original weight row = q*H_ + j. A CTA's 64 cols = 16 units x 4 gates.
__global__ void prep_weights(const float* __restrict__ W_ih,
                             const float* __restrict__ W_hh,
                             const float* __restrict__ b_ih,
                             const float* __restrict__ b_hh)
{
    int idx = blockIdx.x * blockDim.x + threadIdx.x;  // G_*KP threads
    int p = idx / KP, k = idx - p * KP;
    int bn = p >> 6, c = p & 63, u = c >> 2, q = c & 3;
    int j = bn * 16 + u;
    int orig = q * H_ + j;
    float w = 0.f;
    if (k < H_) w = W_hh[orig * H_ + k];
    else if (k < H_ + D_) w = W_ih[orig * D_ + (k - H_)];
    g_Wp[idx] = __float2half(w);
    if (k == 0) g_bp[p] = b_ih[orig] + b_hh[orig];
}

__global__ void prep_xe(const float* __restrict__ src)
{
    int idx = blockIdx.x * blockDim.x + threadIdx.x;  // S_*B_*XP threads
    int t = idx >> 16;            // B_*XP = 65536
    int r = idx & 65535;
    int b = r >> 8, kk = r & 255;
    float v = (kk < D_) ? src[(b * S_ + t) * D_ + kk] : 0.f;
    g_xe[idx] = __float2half(v);
}

__global__ void init_state()
{
    int idx = blockIdx.x * blockDim.x + threadIdx.x;
    if (idx < B_ * H_) {
        g_c[idx] = 0.f;
        g_ah[0][idx] = __float2half(0.f);
    }
    if (idx < B_ * XP) g_xd[idx] = __float2half(0.f);
}

// ---------------- fused LSTM step: fp16 HMMA GEMM + cell ---------------------
// grid (64, 4): blockIdx.x = N tile (64 permuted cols = 16 units),
//               blockIdx.y = M tile (64 batch rows).
// 256 threads = 8 warps arranged 2(M) x 2(N) x 2(K-half). BK=128 chunks
// (10 total) amortize the per-chunk sync/latency toll over 4x the work of R12.
__global__ void __launch_bounds__(256, 2)
lstm_step_mma(int hbuf, int xsel, int xoff)
{
    extern __shared__ __align__(128) char smem[];
    const uint32_t sb = smem_u32(smem);
    const int tid = threadIdx.x;
    const int wid = tid >> 5;
    const int lane = tid & 31;
    const int bn = blockIdx.x;
    const int m0 = blockIdx.y << 6;
    const int n0 = bn << 6;

    const __half* __restrict__ xp = xsel ? g_xd : (g_xe + xoff);

    // ---- hoisted loader bases: 8 cp.async per thread (4 A-rows, 4 B-rows) ---
    const int lrow = tid >> 4;           // 0..15 (rows lrow, +16, +32, +48)
    const int c16  = tid & 15;           // 16B chunk within 256B row
    const __half* aA = g_ah[hbuf] + (size_t)(m0 + lrow) * H_ + c16 * 8;
    const __half* ax = xp + (size_t)(m0 + lrow) * XP + c16 * 8;
    const __half* wB = g_Wp + (size_t)(n0 + lrow) * KP + c16 * 8;
    const uint32_t dA0 = lrow * A_PITCH + c16 * 16;
    const uint32_t dB0 = REGION_BYTES + lrow * A_PITCH + c16 * 16;

    auto load_stage = [&](int ch, int slot) {
        uint32_t s = sb + slot * STAGE_BYTES;
        const __half* a0;
        int astr;
        if (ch < 8) { a0 = aA + ch * BK; astr = 16 * H_; }
        else        { a0 = ax + (ch - 8) * BK; astr = 16 * XP; }
        #pragma unroll
        for (int i = 0; i < 4; i++)
            CP_ASYNC16(s + dA0 + i * (16 * A_PITCH), a0 + i * astr);
        const __half* b0 = wB + ch * BK;
        #pragma unroll
        for (int i = 0; i < 4; i++)
            CP_ASYNC16(s + dB0 + i * (16 * A_PITCH), b0 + (size_t)i * (16 * KP));
    };

    const int kh    = wid & 1;         // K-half (64 of the 128) per warp
    const int warpM = (wid >> 1) & 1;  // rows warpM*32
    const int warpN = wid >> 2;        // cols warpN*32

    // ---- hoisted ldmatrix offsets (within a stage) ----
    const int tsel = lane >> 3;
    const int aRow = (tsel & 1) * 8 + (lane & 7);
    const int aKof = (tsel >> 1) * 16;
    const int bRow = (tsel >> 1) * 8 + (lane & 7);
    const int bKof = (tsel & 1) * 16;
    const uint32_t ra0 = (warpM * 32 + aRow) * A_PITCH + kh * 128 + aKof;
    const uint32_t ra1 = ra0 + 16 * A_PITCH;
    const uint32_t rb0 = REGION_BYTES + (warpN * 32 + bRow) * A_PITCH
                       + kh * 128 + bKof;
    const uint32_t rb1 = rb0 + 16 * A_PITCH;

    float acc[2][4][4];
    #pragma unroll
    for (int mt = 0; mt < 2; mt++)
        #pragma unroll
        for (int j = 0; j < 4; j++)
            #pragma unroll
            for (int q = 0; q < 4; q++) acc[mt][j][q] = 0.f;

    load_stage(0, 0); CP_COMMIT();
    load_stage(1, 1); CP_COMMIT();

    #pragma unroll 1
    for (int ch = 0; ch < NCH; ch++) {
        CP_WAIT1();                 // stage ch resident
        __syncthreads();
        if (ch + 2 < NCH) load_stage(ch + 2, (ch + 2) % NSTAGE);
        CP_COMMIT();

        uint32_t s = sb + (ch % NSTAGE) * STAGE_BYTES;
        #pragma unroll
        for (int kk = 0; kk < 4; kk++) {
            const uint32_t ko = kk * 32;  // 16 fp16 = 32B per k-sub-step
            uint32_t a[2][4];
            LDSM_X4(a[0][0], a[0][1], a[0][2], a[0][3], s + ra0 + ko);
            LDSM_X4(a[1][0], a[1][1], a[1][2], a[1][3], s + ra1 + ko);
            uint32_t b[4][2];
            {
                uint32_t r0, r1, r2, r3;
                LDSM_X4(r0, r1, r2, r3, s + rb0 + ko);
                b[0][0] = r0; b[0][1] = r1; b[1][0] = r2; b[1][1] = r3;
                LDSM_X4(r0, r1, r2, r3, s + rb1 + ko);
                b[2][0] = r0; b[2][1] = r1; b[3][0] = r2; b[3][1] = r3;
            }
            #pragma unroll
            for (int mt = 0; mt < 2; mt++)
                #pragma unroll
                for (int ni = 0; ni < 4; ni++)
                    MMAF16(acc[mt][ni], a[mt], b[ni]);
        }
    }
    CP_WAIT0();
    __syncthreads();

    // ---- epilogue: cross-warp K reduction through smem, fused LSTM cell ----
    float* gbuf = (float*)smem;           // [64][68] f32 = 17.4KB (reuses stages)
    const int GP = 68;
    if (kh == 0) {
        #pragma unroll
        for (int mt = 0; mt < 2; mt++)
            #pragma unroll
            for (int ni = 0; ni < 4; ni++) {
                int r0 = warpM * 32 + mt * 16 + (lane >> 2);
                int c0 = warpN * 32 + ni * 8 + 2 * (lane & 3);
                gbuf[r0 * GP + c0]           = acc[mt][ni][0];
                gbuf[r0 * GP + c0 + 1]       = acc[mt][ni][1];
                gbuf[(r0 + 8) * GP + c0]     = acc[mt][ni][2];
                gbuf[(r0 + 8) * GP + c0 + 1] = acc[mt][ni][3];
            }
    }
    __syncthreads();
    if (kh == 1) {
        #pragma unroll
        for (int mt = 0; mt < 2; mt++)
            #pragma unroll
            for (int ni = 0; ni < 4; ni++) {
                int r0 = warpM * 32 + mt * 16 + (lane >> 2);
                int c0 = warpN * 32 + ni * 8 + 2 * (lane & 3);
                gbuf[r0 * GP + c0]           += acc[mt][ni][0];
                gbuf[r0 * GP + c0 + 1]       += acc[mt][ni][1];
                gbuf[(r0 + 8) * GP + c0]     += acc[mt][ni][2];
                gbuf[(r0 + 8) * GP + c0 + 1] += acc[mt][ni][3];
            }
    }
    __syncthreads();

    {
        const int u = tid & 15;           // local unit 0..15
        const int rg = tid >> 4;          // row group 0..15 (4 rows each)
        const int j = bn * 16 + u;        // global hidden unit
        const float bi = g_bp[n0 + u * 4 + 0];
        const float bf = g_bp[n0 + u * 4 + 1];
        const float bg = g_bp[n0 + u * 4 + 2];
        const float bo = g_bp[n0 + u * 4 + 3];
        __half* __restrict__ oh = g_ah[1 - hbuf];
        #pragma unroll
        for (int rr = 0; rr < 4; rr++) {
            int r = rg * 4 + rr;
            const float* gr = &gbuf[r * GP + u * 4];
            float gi = gr[0] + bi;
            float gf = gr[1] + bf;
            float gg = gr[2] + bg;
            float go = gr[3] + bo;
            size_t idx = (size_t)(m0 + r) * H_ + j;
            float cn = sigf(gf) * g_c[idx] + sigf(gi) * tanhf(gg);
            g_c[idx] = cn;
            float hn = sigf(go) * tanhf(cn);
            g_hf[idx] = hn;
            oh[idx] = __float2half(hn);
        }
    }
}

// ---------------- projection GEMM (fp32, split-K=8; reads g_hf) --------------
__global__ void __launch_bounds__(256, 2)
proj_gemm(const float* __restrict__ Wout)
{
    __shared__ float As[2][8][132];
    __shared__ float Bs[2][8][68];

    const float* __restrict__ h = g_hf;
    int tid = threadIdx.x;
    int n0 = blockIdx.x * 64;
    int m0 = blockIdx.y * 128;
    int ks = blockIdx.z;
    int kbase = ks * 128;

    int lmA = tid >> 1, lkA = (tid & 1) * 4;
    int lmB = tid >> 2, lkB = (tid & 3) * 2;
    int ty = tid >> 4, tx = tid & 15;

    float acc[8][4];
    #pragma unroll
    for (int i = 0; i < 8; i++)
        #pragma unroll
        for (int j = 0; j < 4; j++) acc[i][j] = 0.f;

    float4 aR; float2 bR;
    int dB = n0 + lmB;

    aR = *(const float4*)&h[(m0 + lmA) * H_ + kbase + lkA];
    bR = (dB < D_) ? *(const float2*)&Wout[dB * H_ + kbase + lkB] : make_float2(0.f, 0.f);
    As[0][lkA + 0][lmA] = aR.x; As[0][lkA + 1][lmA] = aR.y;
    As[0][lkA + 2][lmA] = aR.z; As[0][lkA + 3][lmA] = aR.w;
    Bs[0][lkB + 0][lmB] = bR.x; Bs[0][lkB + 1][lmB] = bR.y;
    __syncthreads();

    const int NC = 16;
    for (int ch = 1; ch <= NC; ch++) {
        if (ch < NC) {
            int k0 = kbase + ch * 8;
            aR = *(const float4*)&h[(m0 + lmA) * H_ + k0 + lkA];
            bR = (dB < D_) ? *(const float2*)&Wout[dB * H_ + k0 + lkB] : make_float2(0.f, 0.f);
        }
        int cb = (ch - 1) & 1;
        #pragma unroll
        for (int k = 0; k < 8; k++) {
            float4 a0 = *(const float4*)&As[cb][k][ty * 8];
            float4 a1 = *(const float4*)&As[cb][k][ty * 8 + 4];
            float4 bb = *(const float4*)&Bs[cb][k][tx * 4];
            float av[8] = {a0.x, a0.y, a0.z, a0.w, a1.x, a1.y, a1.z, a1.w};
            float bv[4] = {bb.x, bb.y, bb.z, bb.w};
            #pragma unroll
            for (int i = 0; i < 8; i++)
                #pragma unroll
                for (int j = 0; j < 4; j++)
                    acc[i][j] += av[i] * bv[j];
        }
        if (ch < NC) {
            int sbuf = ch & 1;
            As[sbuf][lkA + 0][lmA] = aR.x; As[sbuf][lkA + 1][lmA] = aR.y;
            As[sbuf][lkA + 2][lmA] = aR.z; As[sbuf][lkA + 3][lmA] = aR.w;
            Bs[sbuf][lkB + 0][lmB] = bR.x; Bs[sbuf][lkB + 1][lmB] = bR.y;
        }
        __syncthreads();
    }

    #pragma unroll
    for (int i = 0; i < 8; i++)
        #pragma unroll
        for (int j = 0; j < 4; j++) {
            int col = n0 + tx * 4 + j;
            if (col < D_)
                g_proj[ks][(m0 + ty * 8 + i) * D_ + col] = acc[i][j];
        }
}

// ---------------- projection reduce: output + decoder-feedback ---------------
__global__ void proj_reduce(const float* __restrict__ b_out,
                            float* __restrict__ out, int t)
{
    int idx = blockIdx.x * blockDim.x + threadIdx.x;
    if (idx >= B_ * D_) return;
    int b = idx / D_;
    int d = idx - b * D_;
    float v = b_out[d];
    #pragma unroll
    for (int s = 0; s < 8; s++) v += g_proj[s][idx];
    out[b * (T_ * D_) + t * D_ + d] = v;
    g_xd[b * XP + d] = __float2half(v);
}

// ---------------- host orchestration ----------------------------------------
extern "C" void kernel_launch(void* const* d_in, const int* in_sizes, int n_in,
                              void* d_out, int out_size)
{
    (void)in_sizes; (void)n_in; (void)out_size;
    const float* src   = (const float*)d_in[0];
    const float* W_ih  = (const float*)d_in[2];
    const float* W_hh  = (const float*)d_in[3];
    const float* b_ih  = (const float*)d_in[4];
    const float* b_hh  = (const float*)d_in[5];
    const float* W_out = (const float*)d_in[6];
    const float* b_out = (const float*)d_in[7];
    float* out = (float*)d_out;

    cudaFuncSetAttribute(lstm_step_mma,
                         cudaFuncAttributeMaxDynamicSharedMemorySize, SMEM_DYN);

    prep_weights<<<(G_ * KP) / 256, 256>>>(W_ih, W_hh, b_ih, b_hh);
    prep_xe<<<(S_ * B_ * XP) / 256, 256>>>(src);
    init_state<<<(B_ * H_) / 256, 256>>>();

    dim3 gg(G_ / 64, B_ / 64);    // (64, 4) = 256 CTAs, 2 per SM
    dim3 pg(4, B_ / 128, 8);
    int cur = 0;

    // Encoder
    for (int t = 0; t < S_; t++) {
        lstm_step_mma<<<gg, 256, SMEM_DYN>>>(cur, 0, t * B_ * XP);
        cur ^= 1;
    }
    // Decoder
    for (int t = 0; t < T_; t++) {
        if (t == 0)
            lstm_step_mma<<<gg, 256, SMEM_DYN>>>(cur, 0, (S_ - 1) * B_ * XP);
        else
            lstm_step_mma<<<gg, 256, SMEM_DYN>>>(cur, 1, 0);
        cur ^= 1;
        proj_gemm<<<pg, 256>>>(W_out);
        proj_reduce<<<(B_ * D_ + 255) / 256, 256>>>(b_out, out, t);
    }
}

// round 15
// speedup vs baseline: 1.0646x; 1.0646x over previous
#include <cuda_runtime.h>
#include <cuda_fp16.h>
#include <math.h>
#include <stdint.h>

#define B_ 256
#define S_ 120
#define T_ 24
#define D_ 216
#define H_ 1024
#define G_ 4096           // 4*H
#define KP 1280           // padded K (1024 h + 216 x + 40 zero)
#define XP 256            // padded x row width
#define BK 64
#define NCH (KP / BK)     // 20
#define A_PITCH 144                    // 128B row + 16B pad (conflict-free)
#define REGION_A 18496                 // 128*144 + 64B rotation
#define REGION_B 9280                  // 64*144 + 64B rotation
#define STAGE_BYTES (REGION_A + REGION_B)  // 27776
#define NSTAGE 3
#define SMEM_DYN (NSTAGE * STAGE_BYTES)    // 83328

// ---------------- device globals (no allocations allowed) --------------------
__device__ __align__(16) __half g_Wp[G_ * KP];        // permuted fp16 weights
__device__ __align__(16) __half g_xe[S_ * B_ * XP];   // encoder x fp16
__device__ __align__(16) __half g_xd[B_ * XP];        // decoder x fp16
__device__ __align__(16) __half g_ah[2][B_ * H_];     // h fp16, ping-pong
__device__ float g_hf[B_ * H_];       // fp32 h (projection input)
__device__ float g_c[B_ * H_];        // cell state
__device__ float g_bp[G_];            // permuted combined bias
__device__ float g_proj[8][B_ * D_];  // split-K projection partials

__device__ __forceinline__ float sigf(float v) { return 1.f / (1.f + expf(-v)); }

// ---------------- PTX helpers (baseline sm_80+ only) -------------------------
__device__ __forceinline__ uint32_t smem_u32(const void* p) {
    uint32_t a;
    asm("{ .reg .u64 t; cvta.to.shared.u64 t, %1; cvt.u32.u64 %0, t; }"
        : "=r"(a) : "l"(p));
    return a;
}
#define CP_ASYNC16(dst, src) \
    asm volatile("cp.async.ca.shared.global [%0], [%1], 16;" :: "r"(dst), "l"(src))
#define CP_COMMIT() asm volatile("cp.async.commit_group;" ::: "memory")
#define CP_WAIT1()  asm volatile("cp.async.wait_group 1;" ::: "memory")
#define CP_WAIT0()  asm volatile("cp.async.wait_group 0;" ::: "memory")

#define LDSM_X4(r0, r1, r2, r3, a) \
    asm volatile("ldmatrix.sync.aligned.m8n8.x4.shared.b16 {%0,%1,%2,%3}, [%4];" \
                 : "=r"(r0), "=r"(r1), "=r"(r2), "=r"(r3) : "r"(a))

#define MMAF16(d, a, b) \
    asm volatile("mma.sync.aligned.m16n8k16.row.col.f32.f16.f16.f32 " \
                 "{%0,%1,%2,%3},{%4,%5,%6,%7},{%8,%9},{%0,%1,%2,%3};" \
                 : "+f"((d)[0]), "+f"((d)[1]), "+f"((d)[2]), "+f"((d)[3]) \
                 : "r"((a)[0]), "r"((a)[1]), "r"((a)[2]), "r"((a)[3]), \
                   "r"((b)[0]), "r"((b)[1]))

// ---------------- prep kernels ----------------------------------------------
// Permutation: permuted col p -> bn=p>>6, c=p&63, u=c>>2, q=c&3, unit j=bn*16+u,
// original weight row = q*H_ + j. A CTA's 64 cols = 16 units x 4 gates.
__global__ void prep_weights(const float* __restrict__ W_ih,
                             const float* __restrict__ W_hh,
                             const float* __restrict__ b_ih,
                             const float* __restrict__ b_hh)
{
    int idx = blockIdx.x * blockDim.x + threadIdx.x;  // G_*KP threads
    int p = idx / KP, k = idx - p * KP;
    int bn = p >> 6, c = p & 63, u = c >> 2, q = c & 3;
    int j = bn * 16 + u;
    int orig = q * H_ + j;
    float w = 0.f;
    if (k < H_) w = W_hh[orig * H_ + k];
    else if (k < H_ + D_) w = W_ih[orig * D_ + (k - H_)];
    g_Wp[idx] = __float2half(w);
    if (k == 0) g_bp[p] = b_ih[orig] + b_hh[orig];
}

__global__ void prep_xe(const float* __restrict__ src)
{
    int idx = blockIdx.x * blockDim.x + threadIdx.x;  // S_*B_*XP threads
    int t = idx >> 16;            // B_*XP = 65536
    int r = idx & 65535;
    int b = r >> 8, kk = r & 255;
    float v = (kk < D_) ? src[(b * S_ + t) * D_ + kk] : 0.f;
    g_xe[idx] = __float2half(v);
}

__global__ void init_state()
{
    int idx = blockIdx.x * blockDim.x + threadIdx.x;
    if (idx < B_ * H_) {
        g_c[idx] = 0.f;
        g_ah[0][idx] = __float2half(0.f);
    }
    if (idx < B_ * XP) g_xd[idx] = __float2half(0.f);
}

// ---------------- fused LSTM step: fp16 HMMA GEMM + cell ---------------------
// grid (64, 2): blockIdx.x = N tile (64 permuted cols = 16 units),
//               blockIdx.y = M tile (128 batch rows).
// 512 threads = 16 warps arranged 4(M) x 2(N) x 2(K-half); warp tile 32x32,
// same per-warp code as the BM=64 version. 1 CTA per SM, grid 128 <= 148 SMs:
// no CTA imbalance, and L2 weight traffic halves (each weight tile read by
// 2 M-CTAs instead of 4).
__global__ void __launch_bounds__(512, 1)
lstm_step_mma(int hbuf, int xsel, int xoff)
{
    extern __shared__ __align__(128) char smem[];
    const uint32_t sb = smem_u32(smem);
    const int tid = threadIdx.x;
    const int wid = tid >> 5;
    const int lane = tid & 31;
    const int bn = blockIdx.x;
    const int m0 = blockIdx.y << 7;      // 128 batch rows per CTA
    const int n0 = bn << 6;

    const __half* __restrict__ xp = xsel ? g_xd : (g_xe + xoff);

    // ---- hoisted loader bases: 3 cp.async per thread (2 A, 1 B) ----
    // A: 128 rows x 128B; thread -> row tid>>2, 32B pair (tid&3)*32
    const int arow = tid >> 2;           // 0..127
    const int ac2  = tid & 3;            // 32B pair within 128B row
    const __half* aA = g_ah[hbuf] + (size_t)(m0 + arow) * H_ + ac2 * 16;
    const __half* ax = xp + (size_t)(m0 + arow) * XP + ac2 * 16;
    const uint32_t dA0 = arow * A_PITCH + ac2 * 32;
    // B: 64 rows x 128B; thread -> row tid>>3, 16B chunk (tid&7)
    const int brow = tid >> 3;           // 0..63
    const int bc8  = tid & 7;
    const __half* wB = g_Wp + (size_t)(n0 + brow) * KP + bc8 * 8;
    const uint32_t dB0 = REGION_A + brow * A_PITCH + bc8 * 16;

    auto load_stage = [&](int ch, int slot) {
        uint32_t s = sb + slot * STAGE_BYTES;
        const __half* a0 = (ch < 16) ? (aA + ch * BK) : (ax + (ch - 16) * BK);
        CP_ASYNC16(s + dA0, a0);
        CP_ASYNC16(s + dA0 + 16, a0 + 8);
        CP_ASYNC16(s + dB0, wB + ch * BK);
    };

    const int kh    = wid & 1;         // K-half (32 of the 64) per warp
    const int warpM = (wid >> 1) & 3;  // rows warpM*32 (4 M-warps)
    const int warpN = wid >> 3;        // cols warpN*32 (2 N-warps)

    // ---- hoisted ldmatrix offsets (within a stage) ----
    const int tsel = lane >> 3;
    const int aRow = (tsel & 1) * 8 + (lane & 7);
    const int aKof = (tsel >> 1) * 16;
    const int bRow = (tsel >> 1) * 8 + (lane & 7);
    const int bKof = (tsel & 1) * 16;
    const uint32_t ra0 = (warpM * 32 + aRow) * A_PITCH + kh * 64 + aKof;
    const uint32_t ra1 = ra0 + 16 * A_PITCH;
    const uint32_t rb0 = REGION_A + (warpN * 32 + bRow) * A_PITCH
                       + kh * 64 + bKof;
    const uint32_t rb1 = rb0 + 16 * A_PITCH;

    float acc[2][4][4];
    #pragma unroll
    for (int mt = 0; mt < 2; mt++)
        #pragma unroll
        for (int j = 0; j < 4; j++)
            #pragma unroll
            for (int q = 0; q < 4; q++) acc[mt][j][q] = 0.f;

    load_stage(0, 0); CP_COMMIT();
    load_stage(1, 1); CP_COMMIT();

    #pragma unroll 1
    for (int ch = 0; ch < NCH; ch++) {
        CP_WAIT1();                 // stage ch resident
        __syncthreads();
        if (ch + 2 < NCH) load_stage(ch + 2, (ch + 2) % NSTAGE);
        CP_COMMIT();

        uint32_t s = sb + (ch % NSTAGE) * STAGE_BYTES;
        #pragma unroll
        for (int kk = 0; kk < 2; kk++) {
            const uint32_t ko = kk * 32;  // 16 fp16 = 32B per k-sub-step
            uint32_t a[2][4];
            LDSM_X4(a[0][0], a[0][1], a[0][2], a[0][3], s + ra0 + ko);
            LDSM_X4(a[1][0], a[1][1], a[1][2], a[1][3], s + ra1 + ko);
            uint32_t b[4][2];
            {
                uint32_t r0, r1, r2, r3;
                LDSM_X4(r0, r1, r2, r3, s + rb0 + ko);
                b[0][0] = r0; b[0][1] = r1; b[1][0] = r2; b[1][1] = r3;
                LDSM_X4(r0, r1, r2, r3, s + rb1 + ko);
                b[2][0] = r0; b[2][1] = r1; b[3][0] = r2; b[3][1] = r3;
            }
            #pragma unroll
            for (int mt = 0; mt < 2; mt++)
                #pragma unroll
                for (int ni = 0; ni < 4; ni++)
                    MMAF16(acc[mt][ni], a[mt], b[ni]);
        }
    }
    CP_WAIT0();
    __syncthreads();

    // ---- epilogue: cross-warp K reduction through smem, fused LSTM cell ----
    float* gbuf = (float*)smem;           // [128][68] f32 = 34.8KB (reuses stages)
    const int GP = 68;
    if (kh == 0) {
        #pragma unroll
        for (int mt = 0; mt < 2; mt++)
            #pragma unroll
            for (int ni = 0; ni < 4; ni++) {
                int r0 = warpM * 32 + mt * 16 + (lane >> 2);
                int c0 = warpN * 32 + ni * 8 + 2 * (lane & 3);
                gbuf[r0 * GP + c0]           = acc[mt][ni][0];
                gbuf[r0 * GP + c0 + 1]       = acc[mt][ni][1];
                gbuf[(r0 + 8) * GP + c0]     = acc[mt][ni][2];
                gbuf[(r0 + 8) * GP + c0 + 1] = acc[mt][ni][3];
            }
    }
    __syncthreads();
    if (kh == 1) {
        #pragma unroll
        for (int mt = 0; mt < 2; mt++)
            #pragma unroll
            for (int ni = 0; ni < 4; ni++) {
                int r0 = warpM * 32 + mt * 16 + (lane >> 2);
                int c0 = warpN * 32 + ni * 8 + 2 * (lane & 3);
                gbuf[r0 * GP + c0]           += acc[mt][ni][0];
                gbuf[r0 * GP + c0 + 1]       += acc[mt][ni][1];
                gbuf[(r0 + 8) * GP + c0]     += acc[mt][ni][2];
                gbuf[(r0 + 8) * GP + c0 + 1] += acc[mt][ni][3];
            }
    }
    __syncthreads();

    {
        const int u = tid & 15;           // local unit 0..15
        const int rg = tid >> 4;          // row group 0..31 (4 rows each)
        const int j = bn * 16 + u;        // global hidden unit
        const float bi = g_bp[n0 + u * 4 + 0];
        const float bf = g_bp[n0 + u * 4 + 1];
        const float bg = g_bp[n0 + u * 4 + 2];
        const float bo = g_bp[n0 + u * 4 + 3];
        __half* __restrict__ oh = g_ah[1 - hbuf];
        #pragma unroll
        for (int rr = 0; rr < 4; rr++) {
            int r = rg * 4 + rr;
            const float* gr = &gbuf[r * GP + u * 4];
            float gi = gr[0] + bi;
            float gf = gr[1] + bf;
            float gg = gr[2] + bg;
            float go = gr[3] + bo;
            size_t idx = (size_t)(m0 + r) * H_ + j;
            float cn = sigf(gf) * g_c[idx] + sigf(gi) * tanhf(gg);
            g_c[idx] = cn;
            float hn = sigf(go) * tanhf(cn);
            g_hf[idx] = hn;
            oh[idx] = __float2half(hn);
        }
    }
}

// ---------------- projection GEMM (fp32, split-K=8; reads g_hf) --------------
__global__ void __launch_bounds__(256, 2)
proj_gemm(const float* __restrict__ Wout)
{
    __shared__ float As[2][8][132];
    __shared__ float Bs[2][8][68];

    const float* __restrict__ h = g_hf;
    int tid = threadIdx.x;
    int n0 = blockIdx.x * 64;
    int m0 = blockIdx.y * 128;
    int ks = blockIdx.z;
    int kbase = ks * 128;

    int lmA = tid >> 1, lkA = (tid & 1) * 4;
    int lmB = tid >> 2, lkB = (tid & 3) * 2;
    int ty = tid >> 4, tx = tid & 15;

    float acc[8][4];
    #pragma unroll
    for (int i = 0; i < 8; i++)
        #pragma unroll
        for (int j = 0; j < 4; j++) acc[i][j] = 0.f;

    float4 aR; float2 bR;
    int dB = n0 + lmB;

    aR = *(const float4*)&h[(m0 + lmA) * H_ + kbase + lkA];
    bR = (dB < D_) ? *(const float2*)&Wout[dB * H_ + kbase + lkB] : make_float2(0.f, 0.f);
    As[0][lkA + 0][lmA] = aR.x; As[0][lkA + 1][lmA] = aR.y;
    As[0][lkA + 2][lmA] = aR.z; As[0][lkA + 3][lmA] = aR.w;
    Bs[0][lkB + 0][lmB] = bR.x; Bs[0][lkB + 1][lmB] = bR.y;
    __syncthreads();

    const int NC = 16;
    for (int ch = 1; ch <= NC; ch++) {
        if (ch < NC) {
            int k0 = kbase + ch * 8;
            aR = *(const float4*)&h[(m0 + lmA) * H_ + k0 + lkA];
            bR = (dB < D_) ? *(const float2*)&Wout[dB * H_ + k0 + lkB] : make_float2(0.f, 0.f);
        }
        int cb = (ch - 1) & 1;
        #pragma unroll
        for (int k = 0; k < 8; k++) {
            float4 a0 = *(const float4*)&As[cb][k][ty * 8];
            float4 a1 = *(const float4*)&As[cb][k][ty * 8 + 4];
            float4 bb = *(const float4*)&Bs[cb][k][tx * 4];
            float av[8] = {a0.x, a0.y, a0.z, a0.w, a1.x, a1.y, a1.z, a1.w};
            float bv[4] = {bb.x, bb.y, bb.z, bb.w};
            #pragma unroll
            for (int i = 0; i < 8; i++)
                #pragma unroll
                for (int j = 0; j < 4; j++)
                    acc[i][j] += av[i] * bv[j];
        }
        if (ch < NC) {
            int sbuf = ch & 1;
            As[sbuf][lkA + 0][lmA] = aR.x; As[sbuf][lkA + 1][lmA] = aR.y;
            As[sbuf][lkA + 2][lmA] = aR.z; As[sbuf][lkA + 3][lmA] = aR.w;
            Bs[sbuf][lkB + 0][lmB] = bR.x; Bs[sbuf][lkB + 1][lmB] = bR.y;
        }
        __syncthreads();
    }

    #pragma unroll
    for (int i = 0; i < 8; i++)
        #pragma unroll
        for (int j = 0; j < 4; j++) {
            int col = n0 + tx * 4 + j;
            if (col < D_)
                g_proj[ks][(m0 + ty * 8 + i) * D_ + col] = acc[i][j];
        }
}

// ---------------- projection reduce: output + decoder-feedback ---------------
__global__ void proj_reduce(const float* __restrict__ b_out,
                            float* __restrict__ out, int t)
{
    int idx = blockIdx.x * blockDim.x + threadIdx.x;
    if (idx >= B_ * D_) return;
    int b = idx / D_;
    int d = idx - b * D_;
    float v = b_out[d];
    #pragma unroll
    for (int s = 0; s < 8; s++) v += g_proj[s][idx];
    out[b * (T_ * D_) + t * D_ + d] = v;
    g_xd[b * XP + d] = __float2half(v);
}

// ---------------- host orchestration ----------------------------------------
extern "C" void kernel_launch(void* const* d_in, const int* in_sizes, int n_in,
                              void* d_out, int out_size)
{
    (void)in_sizes; (void)n_in; (void)out_size;
    const float* src   = (const float*)d_in[0];
    const float* W_ih  = (const float*)d_in[2];
    const float* W_hh  = (const float*)d_in[3];
    const float* b_ih  = (const float*)d_in[4];
    const float* b_hh  = (const float*)d_in[5];
    const float* W_out = (const float*)d_in[6];
    const float* b_out = (const float*)d_in[7];
    float* out = (float*)d_out;

    cudaFuncSetAttribute(lstm_step_mma,
                         cudaFuncAttributeMaxDynamicSharedMemorySize, SMEM_DYN);

    prep_weights<<<(G_ * KP) / 256, 256>>>(W_ih, W_hh, b_ih, b_hh);
    prep_xe<<<(S_ * B_ * XP) / 256, 256>>>(src);
    init_state<<<(B_ * H_) / 256, 256>>>();

    dim3 gg(G_ / 64, B_ / 128);   // (64, 2) = 128 CTAs, 1 per SM
    dim3 pg(4, B_ / 128, 8);
    int cur = 0;

    // Encoder
    for (int t = 0; t < S_; t++) {
        lstm_step_mma<<<gg, 512, SMEM_DYN>>>(cur, 0, t * B_ * XP);
        cur ^= 1;
    }
    // Decoder
    for (int t = 0; t < T_; t++) {
        if (t == 0)
            lstm_step_mma<<<gg, 512, SMEM_DYN>>>(cur, 0, (S_ - 1) * B_ * XP);
        else
            lstm_step_mma<<<gg, 512, SMEM_DYN>>>(cur, 1, 0);
        cur ^= 1;
        proj_gemm<<<pg, 256>>>(W_out);
        proj_reduce<<<(B_ * D_ + 255) / 256, 256>>>(b_out, out, t);
    }
}

// round 16
// speedup vs baseline: 1.1714x; 1.1003x over previous
#include <cuda_runtime.h>
#include <cuda_fp16.h>
#include <math.h>
#include <stdint.h>

#define B_ 256
#define S_ 120
#define T_ 24
#define D_ 216
#define H_ 1024
#define G_ 4096           // 4*H
#define KP 1280           // padded K (1024 h + 216 x + 40 zero)
#define XP 256            // padded x row width
#define BK 64
#define NCH (KP / BK)     // 20
#define A_PITCH 144                    // 128B row + 16B pad (conflict-free)
#define REGION_BYTES 9280              // 64*144 + 64B rotation
#define STAGE_BYTES (2 * REGION_BYTES) // 18560 (A region + B region)
#define NSTAGE 4
#define SMEM_DYN (NSTAGE * STAGE_BYTES)  // 74240

// ---------------- device globals (no allocations allowed) --------------------
__device__ __align__(16) __half g_Wp[G_ * KP];        // permuted fp16 weights
__device__ __align__(16) __half g_xe[S_ * B_ * XP];   // encoder x fp16
__device__ __align__(16) __half g_xd[B_ * XP];        // decoder x fp16
__device__ __align__(16) __half g_ah[2][B_ * H_];     // h fp16, ping-pong
__device__ float g_hf[B_ * H_];       // fp32 h (projection input)
__device__ float g_c[B_ * H_];        // cell state
__device__ float g_bp[G_];            // permuted combined bias
__device__ float g_proj[8][B_ * D_];  // split-K projection partials

__device__ __forceinline__ float sigf(float v) { return 1.f / (1.f + expf(-v)); }

// ---------------- PTX helpers (baseline sm_80+ only) -------------------------
__device__ __forceinline__ uint32_t smem_u32(const void* p) {
    uint32_t a;
    asm("{ .reg .u64 t; cvta.to.shared.u64 t, %1; cvt.u32.u64 %0, t; }"
        : "=r"(a) : "l"(p));
    return a;
}
#define CP_ASYNC16(dst, src) \
    asm volatile("cp.async.ca.shared.global [%0], [%1], 16;" :: "r"(dst), "l"(src))
#define CP_COMMIT() asm volatile("cp.async.commit_group;" ::: "memory")
#define CP_WAIT2()  asm volatile("cp.async.wait_group 2;" ::: "memory")
#define CP_WAIT0()  asm volatile("cp.async.wait_group 0;" ::: "memory")

#define LDSM_X4(r0, r1, r2, r3, a) \
    asm volatile("ldmatrix.sync.aligned.m8n8.x4.shared.b16 {%0,%1,%2,%3}, [%4];" \
                 : "=r"(r0), "=r"(r1), "=r"(r2), "=r"(r3) : "r"(a))

#define MMAF16(d, a, b) \
    asm volatile("mma.sync.aligned.m16n8k16.row.col.f32.f16.f16.f32 " \
                 "{%0,%1,%2,%3},{%4,%5,%6,%7},{%8,%9},{%0,%1,%2,%3};" \
                 : "+f"((d)[0]), "+f"((d)[1]), "+f"((d)[2]), "+f"((d)[3]) \
                 : "r"((a)[0]), "r"((a)[1]), "r"((a)[2]), "r"((a)[3]), \
                   "r"((b)[0]), "r"((b)[1]))

// ---------------- prep kernels ----------------------------------------------
// Permutation: permuted col p -> bn=p>>6, c=p&63, u=c>>2, q=c&3, unit j=bn*16+u,
// original weight row = q*H_ + j. A CTA's 64 cols = 16 units x 4 gates.
__global__ void prep_weights(const float* __restrict__ W_ih,
                             const float* __restrict__ W_hh,
                             const float* __restrict__ b_ih,
                             const float* __restrict__ b_hh)
{
    int idx = blockIdx.x * blockDim.x + threadIdx.x;  // G_*KP threads
    int p = idx / KP, k = idx - p * KP;
    int bn = p >> 6, c = p & 63, u = c >> 2, q = c & 3;
    int j = bn * 16 + u;
    int orig = q * H_ + j;
    float w = 0.f;
    if (k < H_) w = W_hh[orig * H_ + k];
    else if (k < H_ + D_) w = W_ih[orig * D_ + (k - H_)];
    g_Wp[idx] = __float2half(w);
    if (k == 0) g_bp[p] = b_ih[orig] + b_hh[orig];
}

__global__ void prep_xe(const float* __restrict__ src)
{
    int idx = blockIdx.x * blockDim.x + threadIdx.x;  // S_*B_*XP threads
    int t = idx >> 16;            // B_*XP = 65536
    int r = idx & 65535;
    int b = r >> 8, kk = r & 255;
    float v = (kk < D_) ? src[(b * S_ + t) * D_ + kk] : 0.f;
    g_xe[idx] = __float2half(v);
}

__global__ void init_state()
{
    int idx = blockIdx.x * blockDim.x + threadIdx.x;
    if (idx < B_ * H_) {
        g_c[idx] = 0.f;
        g_ah[0][idx] = __float2half(0.f);
    }
    if (idx < B_ * XP) g_xd[idx] = __float2half(0.f);
}

// ---------------- fused LSTM step: fp16 HMMA GEMM + cell ---------------------
// grid (64, 4): blockIdx.x = N tile (64 permuted cols = 16 units),
//               blockIdx.y = M tile (64 batch rows).
// 256 threads = 8 warps arranged 2(M) x 2(N) x 2(K-half). BK=64 chunks (20),
// 4-stage ring with CP_WAIT2 (3 chunks in flight -> wait observes a landed
// group), and both k-sub fragment sets LDSM'd before any MMA so the second
// half's load latency hides under the first half's MMAs.
__global__ void __launch_bounds__(256, 2)
lstm_step_mma(int hbuf, int xsel, int xoff)
{
    extern __shared__ __align__(128) char smem[];
    const uint32_t sb = smem_u32(smem);
    const int tid = threadIdx.x;
    const int wid = tid >> 5;
    const int lane = tid & 31;
    const int bn = blockIdx.x;
    const int m0 = blockIdx.y << 6;
    const int n0 = bn << 6;

    const __half* __restrict__ xp = xsel ? g_xd : (g_xe + xoff);

    // ---- hoisted loader bases: 4 cp.async per thread (2 A-rows, 2 B-rows) ---
    const int r0l = tid >> 3;            // 0..31 (rows r0l and r0l+32)
    const int c8  = tid & 7;             // 16B chunk within 128B row
    const __half* aA = g_ah[hbuf] + (size_t)(m0 + r0l) * H_ + c8 * 8;
    const __half* ax = xp + (size_t)(m0 + r0l) * XP + c8 * 8;
    const __half* wB = g_Wp + (size_t)(n0 + r0l) * KP + c8 * 8;
    const uint32_t dA0 = r0l * A_PITCH + c8 * 16;
    const uint32_t dB0 = REGION_BYTES + r0l * A_PITCH + c8 * 16;

    auto load_stage = [&](int ch, int slot) {
        uint32_t s = sb + slot * STAGE_BYTES;
        const __half* a0;
        int astr;
        if (ch < 16) { a0 = aA + ch * BK; astr = 32 * H_; }
        else         { a0 = ax + (ch - 16) * BK; astr = 32 * XP; }
        CP_ASYNC16(s + dA0, a0);
        CP_ASYNC16(s + dA0 + 32 * A_PITCH, a0 + astr);
        const __half* b0 = wB + ch * BK;
        CP_ASYNC16(s + dB0, b0);
        CP_ASYNC16(s + dB0 + 32 * A_PITCH, b0 + (size_t)32 * KP);
    };

    const int kh    = wid & 1;         // K-half (32 of the 64) per warp
    const int warpM = (wid >> 1) & 1;  // rows warpM*32
    const int warpN = wid >> 2;        // cols warpN*32

    // ---- hoisted ldmatrix offsets (within a stage) ----
    const int tsel = lane >> 3;
    const int aRow = (tsel & 1) * 8 + (lane & 7);
    const int aKof = (tsel >> 1) * 16;
    const int bRow = (tsel >> 1) * 8 + (lane & 7);
    const int bKof = (tsel & 1) * 16;
    const uint32_t ra0 = (warpM * 32 + aRow) * A_PITCH + kh * 64 + aKof;
    const uint32_t ra1 = ra0 + 16 * A_PITCH;
    const uint32_t rb0 = REGION_BYTES + (warpN * 32 + bRow) * A_PITCH
                       + kh * 64 + bKof;
    const uint32_t rb1 = rb0 + 16 * A_PITCH;

    float acc[2][4][4];
    #pragma unroll
    for (int mt = 0; mt < 2; mt++)
        #pragma unroll
        for (int j = 0; j < 4; j++)
            #pragma unroll
            for (int q = 0; q < 4; q++) acc[mt][j][q] = 0.f;

    load_stage(0, 0); CP_COMMIT();
    load_stage(1, 1); CP_COMMIT();
    load_stage(2, 2); CP_COMMIT();

    #pragma unroll 1
    for (int ch = 0; ch < NCH; ch++) {
        CP_WAIT2();                 // stage ch resident (3 groups in flight)
        __syncthreads();
        if (ch + 3 < NCH) load_stage(ch + 3, (ch + 3) & 3);
        CP_COMMIT();

        uint32_t s = sb + (ch & 3) * STAGE_BYTES;
        // preload BOTH k-sub fragment sets, then run all MMAs: the second
        // LDSM batch's latency hides under the first batch's MMAs.
        uint32_t a0f[2][4], a1f[2][4], b0f[4][2], b1f[4][2];
        LDSM_X4(a0f[0][0], a0f[0][1], a0f[0][2], a0f[0][3], s + ra0);
        LDSM_X4(a0f[1][0], a0f[1][1], a0f[1][2], a0f[1][3], s + ra1);
        {
            uint32_t r0, r1, r2, r3;
            LDSM_X4(r0, r1, r2, r3, s + rb0);
            b0f[0][0] = r0; b0f[0][1] = r1; b0f[1][0] = r2; b0f[1][1] = r3;
            LDSM_X4(r0, r1, r2, r3, s + rb1);
            b0f[2][0] = r0; b0f[2][1] = r1; b0f[3][0] = r2; b0f[3][1] = r3;
        }
        LDSM_X4(a1f[0][0], a1f[0][1], a1f[0][2], a1f[0][3], s + ra0 + 32);
        LDSM_X4(a1f[1][0], a1f[1][1], a1f[1][2], a1f[1][3], s + ra1 + 32);
        {
            uint32_t r0, r1, r2, r3;
            LDSM_X4(r0, r1, r2, r3, s + rb0 + 32);
            b1f[0][0] = r0; b1f[0][1] = r1; b1f[1][0] = r2; b1f[1][1] = r3;
            LDSM_X4(r0, r1, r2, r3, s + rb1 + 32);
            b1f[2][0] = r0; b1f[2][1] = r1; b1f[3][0] = r2; b1f[3][1] = r3;
        }
        #pragma unroll
        for (int mt = 0; mt < 2; mt++)
            #pragma unroll
            for (int ni = 0; ni < 4; ni++)
                MMAF16(acc[mt][ni], a0f[mt], b0f[ni]);
        #pragma unroll
        for (int mt = 0; mt < 2; mt++)
            #pragma unroll
            for (int ni = 0; ni < 4; ni++)
                MMAF16(acc[mt][ni], a1f[mt], b1f[ni]);
    }
    CP_WAIT0();
    __syncthreads();

    // ---- epilogue: cross-warp K reduction through smem, fused LSTM cell ----
    float* gbuf = (float*)smem;           // [64][68] f32 = 17.4KB (reuses stages)
    const int GP = 68;
    if (kh == 0) {
        #pragma unroll
        for (int mt = 0; mt < 2; mt++)
            #pragma unroll
            for (int ni = 0; ni < 4; ni++) {
                int r0 = warpM * 32 + mt * 16 + (lane >> 2);
                int c0 = warpN * 32 + ni * 8 + 2 * (lane & 3);
                gbuf[r0 * GP + c0]           = acc[mt][ni][0];
                gbuf[r0 * GP + c0 + 1]       = acc[mt][ni][1];
                gbuf[(r0 + 8) * GP + c0]     = acc[mt][ni][2];
                gbuf[(r0 + 8) * GP + c0 + 1] = acc[mt][ni][3];
            }
    }
    __syncthreads();
    if (kh == 1) {
        #pragma unroll
        for (int mt = 0; mt < 2; mt++)
            #pragma unroll
            for (int ni = 0; ni < 4; ni++) {
                int r0 = warpM * 32 + mt * 16 + (lane >> 2);
                int c0 = warpN * 32 + ni * 8 + 2 * (lane & 3);
                gbuf[r0 * GP + c0]           += acc[mt][ni][0];
                gbuf[r0 * GP + c0 + 1]       += acc[mt][ni][1];
                gbuf[(r0 + 8) * GP + c0]     += acc[mt][ni][2];
                gbuf[(r0 + 8) * GP + c0 + 1] += acc[mt][ni][3];
            }
    }
    __syncthreads();

    {
        const int u = tid & 15;           // local unit 0..15
        const int rg = tid >> 4;          // row group 0..15 (4 rows each)
        const int j = bn * 16 + u;        // global hidden unit
        const float bi = g_bp[n0 + u * 4 + 0];
        const float bf = g_bp[n0 + u * 4 + 1];
        const float bg = g_bp[n0 + u * 4 + 2];
        const float bo = g_bp[n0 + u * 4 + 3];
        __half* __restrict__ oh = g_ah[1 - hbuf];
        #pragma unroll
        for (int rr = 0; rr < 4; rr++) {
            int r = rg * 4 + rr;
            const float* gr = &gbuf[r * GP + u * 4];
            float gi = gr[0] + bi;
            float gf = gr[1] + bf;
            float gg = gr[2] + bg;
            float go = gr[3] + bo;
            size_t idx = (size_t)(m0 + r) * H_ + j;
            float cn = sigf(gf) * g_c[idx] + sigf(gi) * tanhf(gg);
            g_c[idx] = cn;
            float hn = sigf(go) * tanhf(cn);
            g_hf[idx] = hn;
            oh[idx] = __float2half(hn);
        }
    }
}

// ---------------- projection GEMM (fp32, split-K=8; reads g_hf) --------------
__global__ void __launch_bounds__(256, 2)
proj_gemm(const float* __restrict__ Wout)
{
    __shared__ float As[2][8][132];
    __shared__ float Bs[2][8][68];

    const float* __restrict__ h = g_hf;
    int tid = threadIdx.x;
    int n0 = blockIdx.x * 64;
    int m0 = blockIdx.y * 128;
    int ks = blockIdx.z;
    int kbase = ks * 128;

    int lmA = tid >> 1, lkA = (tid & 1) * 4;
    int lmB = tid >> 2, lkB = (tid & 3) * 2;
    int ty = tid >> 4, tx = tid & 15;

    float acc[8][4];
    #pragma unroll
    for (int i = 0; i < 8; i++)
        #pragma unroll
        for (int j = 0; j < 4; j++) acc[i][j] = 0.f;

    float4 aR; float2 bR;
    int dB = n0 + lmB;

    aR = *(const float4*)&h[(m0 + lmA) * H_ + kbase + lkA];
    bR = (dB < D_) ? *(const float2*)&Wout[dB * H_ + kbase + lkB] : make_float2(0.f, 0.f);
    As[0][lkA + 0][lmA] = aR.x; As[0][lkA + 1][lmA] = aR.y;
    As[0][lkA + 2][lmA] = aR.z; As[0][lkA + 3][lmA] = aR.w;
    Bs[0][lkB + 0][lmB] = bR.x; Bs[0][lkB + 1][lmB] = bR.y;
    __syncthreads();

    const int NC = 16;
    for (int ch = 1; ch <= NC; ch++) {
        if (ch < NC) {
            int k0 = kbase + ch * 8;
            aR = *(const float4*)&h[(m0 + lmA) * H_ + k0 + lkA];
            bR = (dB < D_) ? *(const float2*)&Wout[dB * H_ + k0 + lkB] : make_float2(0.f, 0.f);
        }
        int cb = (ch - 1) & 1;
        #pragma unroll
        for (int k = 0; k < 8; k++) {
            float4 a0 = *(const float4*)&As[cb][k][ty * 8];
            float4 a1 = *(const float4*)&As[cb][k][ty * 8 + 4];
            float4 bb = *(const float4*)&Bs[cb][k][tx * 4];
            float av[8] = {a0.x, a0.y, a0.z, a0.w, a1.x, a1.y, a1.z, a1.w};
            float bv[4] = {bb.x, bb.y, bb.z, bb.w};
            #pragma unroll
            for (int i = 0; i < 8; i++)
                #pragma unroll
                for (int j = 0; j < 4; j++)
                    acc[i][j] += av[i] * bv[j];
        }
        if (ch < NC) {
            int sbuf = ch & 1;
            As[sbuf][lkA + 0][lmA] = aR.x; As[sbuf][lkA + 1][lmA] = aR.y;
            As[sbuf][lkA + 2][lmA] = aR.z; As[sbuf][lkA + 3][lmA] = aR.w;
            Bs[sbuf][lkB + 0][lmB] = bR.x; Bs[sbuf][lkB + 1][lmB] = bR.y;
        }
        __syncthreads();
    }

    #pragma unroll
    for (int i = 0; i < 8; i++)
        #pragma unroll
        for (int j = 0; j < 4; j++) {
            int col = n0 + tx * 4 + j;
            if (col < D_)
                g_proj[ks][(m0 + ty * 8 + i) * D_ + col] = acc[i][j];
        }
}

// ---------------- projection reduce: output + decoder-feedback ---------------
__global__ void proj_reduce(const float* __restrict__ b_out,
                            float* __restrict__ out, int t)
{
    int idx = blockIdx.x * blockDim.x + threadIdx.x;
    if (idx >= B_ * D_) return;
    int b = idx / D_;
    int d = idx - b * D_;
    float v = b_out[d];
    #pragma unroll
    for (int s = 0; s < 8; s++) v += g_proj[s][idx];
    out[b * (T_ * D_) + t * D_ + d] = v;
    g_xd[b * XP + d] = __float2half(v);
}

// ---------------- host orchestration ----------------------------------------
extern "C" void kernel_launch(void* const* d_in, const int* in_sizes, int n_in,
                              void* d_out, int out_size)
{
    (void)in_sizes; (void)n_in; (void)out_size;
    const float* src   = (const float*)d_in[0];
    const float* W_ih  = (const float*)d_in[2];
    const float* W_hh  = (const float*)d_in[3];
    const float* b_ih  = (const float*)d_in[4];
    const float* b_hh  = (const float*)d_in[5];
    const float* W_out = (const float*)d_in[6];
    const float* b_out = (const float*)d_in[7];
    float* out = (float*)d_out;

    cudaFuncSetAttribute(lstm_step_mma,
                         cudaFuncAttributeMaxDynamicSharedMemorySize, SMEM_DYN);

    prep_weights<<<(G_ * KP) / 256, 256>>>(W_ih, W_hh, b_ih, b_hh);
    prep_xe<<<(S_ * B_ * XP) / 256, 256>>>(src);
    init_state<<<(B_ * H_) / 256, 256>>>();

    dim3 gg(G_ / 64, B_ / 64);    // (64, 4) = 256 CTAs, 2 per SM
    dim3 pg(4, B_ / 128, 8);
    int cur = 0;

    // Encoder
    for (int t = 0; t < S_; t++) {
        lstm_step_mma<<<gg, 256, SMEM_DYN>>>(cur, 0, t * B_ * XP);
        cur ^= 1;
    }
    // Decoder
    for (int t = 0; t < T_; t++) {
        if (t == 0)
            lstm_step_mma<<<gg, 256, SMEM_DYN>>>(cur, 0, (S_ - 1) * B_ * XP);
        else
            lstm_step_mma<<<gg, 256, SMEM_DYN>>>(cur, 1, 0);
        cur ^= 1;
        proj_gemm<<<pg, 256>>>(W_out);
        proj_reduce<<<(B_ * D_ + 255) / 256, 256>>>(b_out, out, t);
    }
}